// round 10
// baseline (speedup 1.0000x reference)
#include <cuda_runtime.h>

#define T_STEPS 8192
#define UNITS   2048
#define INDIM   512
#define RNN_BLOCKS 128
#define ROWS_PB 16          // UNITS / RNN_BLOCKS
#define FLAG_STRIDE 32      // 128B line per flag

__device__ unsigned g_flags[RNN_BLOCKS * FLAG_STRIDE];
__device__ float g_xin[(size_t)T_STEPS * UNITS];   // 64 MB scratch

// ---------------------------------------------------------------------------
// Kernel 1: xin[t][u] = dot(x[t], wax[u]) + ba[u]   (also zeroes the barrier
// flags each launch so the persistent kernel's flag protocol is replay-safe).
// ---------------------------------------------------------------------------
__global__ void __launch_bounds__(256) xin_gemm(const float* __restrict__ x,
                                                const float* __restrict__ wax,
                                                const float* __restrict__ ba) {
    __shared__ float As[8][128];
    __shared__ float Bs[8][128];
    const int tid = threadIdx.x;
    if (blockIdx.x == 0 && blockIdx.y == 0 && tid < RNN_BLOCKS)
        g_flags[tid * FLAG_STRIDE] = 0u;

    const int t0 = blockIdx.y * 128;
    const int u0 = blockIdx.x * 128;
    const int lr = tid >> 1;
    const int lk = (tid & 1) * 4;
    const float* xg = x   + (size_t)(t0 + lr) * INDIM + lk;
    const float* wg = wax + (size_t)(u0 + lr) * INDIM + lk;
    const int ty = tid >> 4, tx = tid & 15;
    const int m = ty * 8, n = tx * 8;

    unsigned long long cc[8][4];
#pragma unroll
    for (int i = 0; i < 8; i++)
#pragma unroll
        for (int j = 0; j < 4; j++) cc[i][j] = 0ULL;

    for (int k0 = 0; k0 < INDIM; k0 += 8) {
        float4 av = *(const float4*)(xg + k0);
        float4 bv = *(const float4*)(wg + k0);
        As[lk + 0][lr] = av.x; As[lk + 1][lr] = av.y;
        As[lk + 2][lr] = av.z; As[lk + 3][lr] = av.w;
        Bs[lk + 0][lr] = bv.x; Bs[lk + 1][lr] = bv.y;
        Bs[lk + 2][lr] = bv.z; Bs[lk + 3][lr] = bv.w;
        __syncthreads();
#pragma unroll
        for (int k = 0; k < 8; k++) {
            float4 a0 = *(const float4*)&As[k][m];
            float4 a1 = *(const float4*)&As[k][m + 4];
            ulonglong2 b0 = *(const ulonglong2*)&Bs[k][n];
            ulonglong2 b1 = *(const ulonglong2*)&Bs[k][n + 4];
            float aa[8] = {a0.x, a0.y, a0.z, a0.w, a1.x, a1.y, a1.z, a1.w};
            unsigned long long bb[4] = {b0.x, b0.y, b1.x, b1.y};
#pragma unroll
            for (int i = 0; i < 8; i++) {
                unsigned ai = __float_as_uint(aa[i]);
                unsigned long long ad;
                asm("mov.b64 %0, {%1, %1};" : "=l"(ad) : "r"(ai));
#pragma unroll
                for (int j = 0; j < 4; j++)
                    asm("fma.rn.f32x2 %0, %1, %2, %0;"
                        : "+l"(cc[i][j]) : "l"(ad), "l"(bb[j]));
            }
        }
        __syncthreads();
    }
#pragma unroll
    for (int i = 0; i < 8; i++) {
#pragma unroll
        for (int j = 0; j < 4; j++) {
            int uu = u0 + n + j * 2;
            float lo = __uint_as_float((unsigned)(cc[i][j])) + ba[uu];
            float hi = __uint_as_float((unsigned)(cc[i][j] >> 32)) + ba[uu + 1];
            *(float2*)&g_xin[(size_t)(t0 + m + i) * UNITS + uu] = make_float2(lo, hi);
        }
    }
}

// ---------------------------------------------------------------------------
// Kernel 2: persistent RNN scan. 128 CTAs x 1024 threads, waa in registers.
// Per-warp a-slice staging (no block sync), register xin pipeline,
// flag-array release/acquire grid barrier.
// ---------------------------------------------------------------------------
__global__ void __launch_bounds__(1024, 1) rnn_kernel(const float* __restrict__ waa,
                                                      float* __restrict__ out) {
    __shared__ float sa[32][64];           // per-warp a slice
    __shared__ float red[32][17];          // cross-warp partials (padded)

    const int tid = threadIdx.x;
    const int w = tid >> 5;
    const int l = tid & 31;
    const int r = l & 15;                  // local row 0..15
    const int h = l >> 4;                  // column half 0/1
    const int cb = w * 64 + h * 32;        // this thread's column base
    const int r0 = blockIdx.x * ROWS_PB;
    const int row = r0 + r;

    // 32 waa coefficients as 16 f32x2 pairs (order matches sa[w][h*32+...]).
    unsigned long long wreg[16];
    {
        const unsigned long long* wp =
            (const unsigned long long*)(waa + (size_t)row * UNITS + cb);
#pragma unroll
        for (int i = 0; i < 16; i++) wreg[i] = wp[i];
    }

    // xin register pipeline: only (w<16, l==0) lanes consume it.
    const bool xl = (w < 16) && (l == 0);
    float x_cur = 0.f;
    if (xl) x_cur = g_xin[r0 + w];

    for (int t = 0; t < T_STEPS; t++) {
        // prefetch xin[t+1] into register (consumed next iteration, >1 step gap)
        float x_nxt = 0.f;
        if (xl && t + 1 < T_STEPS)
            x_nxt = g_xin[(size_t)(t + 1) * UNITS + r0 + w];

        // --- per-warp stage of this warp's 64-column a slice ---
        if (t == 0) {
            sa[w][2 * l] = 0.f; sa[w][2 * l + 1] = 0.f;
        } else {
            float2 v = *(const float2*)(out + (size_t)(t - 1) * UNITS + w * 64 + 2 * l);
            sa[w][2 * l] = v.x; sa[w][2 * l + 1] = v.y;
        }
        __syncwarp();

        // --- partial dot: 32 MACs as 2 chains of 8 FFMA2, LDS.128 feeds ---
        unsigned long long acc0 = 0ULL, acc1 = 0ULL;
        const float* ap = &sa[w][h * 32];
#pragma unroll
        for (int j = 0; j < 8; j++) {
            float4 q = *(const float4*)(ap + j * 4);
            unsigned long long a01, a23;
            asm("mov.b64 %0, {%1, %2};" : "=l"(a01) : "r"(__float_as_uint(q.x)), "r"(__float_as_uint(q.y)));
            asm("mov.b64 %0, {%1, %2};" : "=l"(a23) : "r"(__float_as_uint(q.z)), "r"(__float_as_uint(q.w)));
            asm("fma.rn.f32x2 %0, %1, %2, %0;" : "+l"(acc0) : "l"(wreg[2 * j]),     "l"(a01));
            asm("fma.rn.f32x2 %0, %1, %2, %0;" : "+l"(acc1) : "l"(wreg[2 * j + 1]), "l"(a23));
        }
        float s = __uint_as_float((unsigned)acc0) + __uint_as_float((unsigned)(acc0 >> 32))
                + __uint_as_float((unsigned)acc1) + __uint_as_float((unsigned)(acc1 >> 32));
        // merge the two column halves (lanes r and r+16 share a row)
        s += __shfl_xor_sync(0xffffffffu, s, 16);
        if (l < 16) red[w][l] = s;
        __syncthreads();

        // --- phase 2: warp r reduces 32 warp-partials for row r ---
        if (w < 16) {
            float v = red[l][w];
            v += __shfl_xor_sync(0xffffffffu, v, 16);
            v += __shfl_xor_sync(0xffffffffu, v, 8);
            v += __shfl_xor_sync(0xffffffffu, v, 4);
            v += __shfl_xor_sync(0xffffffffu, v, 2);
            v += __shfl_xor_sync(0xffffffffu, v, 1);
            if (l == 0) {
                float y = tanhf(v + x_cur);
                out[(size_t)t * UNITS + r0 + w] = y;
            }
        }
        __syncthreads();   // out[t] stores done before flag release; red reusable

        // --- flag-array grid barrier ---
        if (t + 1 < T_STEPS) {
            unsigned tt = (unsigned)(t + 1);
            if (tid == 0) {
                unsigned* fp = &g_flags[blockIdx.x * FLAG_STRIDE];
                asm volatile("st.release.gpu.u32 [%0], %1;" :: "l"(fp), "r"(tt) : "memory");
            }
            if (tid < RNN_BLOCKS) {
                unsigned* fp = &g_flags[tid * FLAG_STRIDE];
                unsigned v;
                do {
                    asm volatile("ld.acquire.gpu.u32 %0, [%1];" : "=r"(v) : "l"(fp) : "memory");
                } while (v < tt);
            }
            __syncthreads();
        }
        x_cur = x_nxt;
    }
}

extern "C" void kernel_launch(void* const* d_in, const int* in_sizes, int n_in,
                              void* d_out, int out_size) {
    const float* x   = (const float*)d_in[0];   // [1, 8192, 512]
    const float* waa = (const float*)d_in[1];   // [2048, 2048]
    const float* wax = (const float*)d_in[2];   // [2048, 512]
    const float* ba  = (const float*)d_in[3];   // [2048, 1]
    float* out = (float*)d_out;                  // [1, 8192, 2048]

    dim3 gg(UNITS / 128, T_STEPS / 128);
    xin_gemm<<<gg, 256>>>(x, wax, ba);
    rnn_kernel<<<RNN_BLOCKS, 1024>>>(waa, out);
}